// round 1
// baseline (speedup 1.0000x reference)
#include <cuda_runtime.h>

#define BATCH 16
#define IC    512
#define OC    512
#define WD    512
#define HIN   32
#define RES   64
#define YS    65      // intermediate (upsampled) size: 2*32+3-2

#define OCT 32        // oc per block in main conv
#define ICC 8         // ic chunk

// ---- scratch (device globals: no runtime allocation allowed) ----
__device__ float g_styles[BATCH * IC];
__device__ float g_dcoef [BATCH * OC];
__device__ float g_wsum  [OC * IC];
__device__ float g_y     [(size_t)BATCH * OC * YS * YS];   // ~138 MB

// ---------------------------------------------------------------------------
// K1: styles[b,ic] = (1/sqrt(WD)) * sum_wd w[b,wd]*aw[ic,wd] + ab[ic]
// one warp per (b, ic)
// ---------------------------------------------------------------------------
__global__ void k_styles(const float* __restrict__ w,
                         const float* __restrict__ aw,
                         const float* __restrict__ ab) {
    int b    = blockIdx.y;
    int warp = threadIdx.x >> 5;
    int lane = threadIdx.x & 31;
    int ic   = blockIdx.x * 8 + warp;
    const float* wrow = w  + (size_t)b  * WD;
    const float* arow = aw + (size_t)ic * WD;
    float s = 0.f;
    #pragma unroll 4
    for (int k = lane; k < WD; k += 32) s += wrow[k] * arow[k];
    #pragma unroll
    for (int o = 16; o; o >>= 1) s += __shfl_xor_sync(0xffffffffu, s, o);
    if (lane == 0)
        g_styles[b * IC + ic] = s * 0.04419417382415922f /* 1/sqrt(512) */ + ab[ic];
}

// ---------------------------------------------------------------------------
// K2: wsum[oc,ic] = sum over 3x3 of conv_weight^2
// ---------------------------------------------------------------------------
__global__ void k_wsum(const float* __restrict__ cw) {
    int idx = blockIdx.x * blockDim.x + threadIdx.x;   // oc*IC+ic
    if (idx >= OC * IC) return;
    const float* p = cw + (size_t)idx * 9;
    float s = 0.f;
    #pragma unroll
    for (int k = 0; k < 9; k++) { float v = p[k]; s += v * v; }
    g_wsum[idx] = s;
}

// ---------------------------------------------------------------------------
// K3: dcoef[b,oc] = rsqrt(sum_ic styles[b,ic]^2 * wsum[oc,ic] + 1e-8)
// one warp per (b, oc)
// ---------------------------------------------------------------------------
__global__ void k_dcoef() {
    int b    = blockIdx.y;
    int warp = threadIdx.x >> 5;
    int lane = threadIdx.x & 31;
    int oc   = blockIdx.x * 8 + warp;
    float s = 0.f;
    #pragma unroll 4
    for (int ic = lane; ic < IC; ic += 32) {
        float st = g_styles[b * IC + ic];
        s += st * st * g_wsum[oc * IC + ic];
    }
    #pragma unroll
    for (int o = 16; o; o >>= 1) s += __shfl_xor_sync(0xffffffffu, s, o);
    if (lane == 0) g_dcoef[b * OC + oc] = rsqrtf(s + 1e-8f);
}

// ---------------------------------------------------------------------------
// K4: grouped transpose conv, stride 2, k=3, parity-decomposed gather form:
//   y[b,oc,p,q] = dcoef[b,oc] * sum_ic sum_{i,j: i==p mod2, j==q mod2}
//                 (x[b,ic,(p-i)/2,(q-j)/2]*styles[b,ic]) * cw[oc,ic,i,j]
// Block: 32 oc x 16x16 y-tile. Thread: (ocl, rowgroup) -> 2 rows x 16 cols.
// ---------------------------------------------------------------------------
__global__ void k_conv(const float* __restrict__ x, const float* __restrict__ cw) {
    __shared__ float sx[ICC][9][10];      // x tile (style-scaled), halo'd, padded
    __shared__ float sw[OCT][ICC][9];     // raw conv weights

    int z   = blockIdx.z;
    int b   = z >> 4;
    int oc0 = (z & 15) * OCT;
    int P0  = blockIdx.y * 16;
    int Q0  = blockIdx.x * 16;
    int H0  = P0 >> 1;
    int W0  = Q0 >> 1;
    int tid = threadIdx.x;
    int ocl = tid >> 3;     // 0..31
    int rg  = tid & 7;      // 0..7: handles y rows P0+2rg (even) and +1 (odd)

    float acc0[16], acc1[16];
    #pragma unroll
    for (int c = 0; c < 16; c++) { acc0[c] = 0.f; acc1[c] = 0.f; }

    for (int ic0 = 0; ic0 < IC; ic0 += ICC) {
        // ---- load x tile (9x9 spatial, ICC channels), scaled by styles ----
        for (int i = tid; i < ICC * 81; i += 256) {
            int icl = i / 81;
            int rem = i - icl * 81;
            int r = rem / 9, c = rem - (rem / 9) * 9;
            int h = H0 - 1 + r, wc = W0 - 1 + c;
            float v = 0.f;
            if (h >= 0 && h < HIN && wc >= 0 && wc < HIN)
                v = x[(((size_t)b * IC + ic0 + icl) * HIN + h) * HIN + wc]
                    * g_styles[b * IC + ic0 + icl];
            sx[icl][r][c] = v;
        }
        // ---- load weight chunk ----
        for (int i = tid; i < OCT * ICC * 9; i += 256) {
            int o   = i / 72;
            int rem = i - o * 72;
            sw[o][rem / 9][rem % 9] =
                cw[((size_t)(oc0 + o) * IC + ic0 + rem / 9) * 9 + (rem % 9)];
        }
        __syncthreads();

        for (int icl = 0; icl < ICC; icl++) {
            float xa[9], xb[9];
            #pragma unroll
            for (int c = 0; c < 9; c++) { xa[c] = sx[icl][rg][c]; xb[c] = sx[icl][rg + 1][c]; }
            float w0 = sw[ocl][icl][0], w1 = sw[ocl][icl][1], w2 = sw[ocl][icl][2];
            float w3 = sw[ocl][icl][3], w4 = sw[ocl][icl][4], w5 = sw[ocl][icl][5];
            float w6 = sw[ocl][icl][6], w7 = sw[ocl][icl][7], w8 = sw[ocl][icl][8];
            #pragma unroll
            for (int m = 0; m < 8; m++) {
                // even col (q = Q0+2m): taps j in {0,2}
                acc0[2 * m]     += w0 * xb[m + 1] + w2 * xb[m] + w6 * xa[m + 1] + w8 * xa[m];
                acc1[2 * m]     += w3 * xb[m + 1] + w5 * xb[m];
                // odd col (q = Q0+2m+1): tap j = 1
                acc0[2 * m + 1] += w1 * xb[m + 1] + w7 * xa[m + 1];
                acc1[2 * m + 1] += w4 * xb[m + 1];
            }
        }
        __syncthreads();
    }

    float dco = g_dcoef[b * OC + oc0 + ocl];
    int p0 = P0 + 2 * rg;
    size_t base = ((size_t)b * OC + oc0 + ocl) * YS;
    if (p0 < YS) {
        size_t row = (base + p0) * YS;
        #pragma unroll
        for (int c = 0; c < 16; c++) {
            int q = Q0 + c;
            if (q < YS) g_y[row + q] = acc0[c] * dco;
        }
    }
    if (p0 + 1 < YS) {
        size_t row = (base + p0 + 1) * YS;
        #pragma unroll
        for (int c = 0; c < 16; c++) {
            int q = Q0 + c;
            if (q < YS) g_y[row + q] = acc1[c] * dco;
        }
    }
}

// ---------------------------------------------------------------------------
// K5: upfirdn (pad 1, 4x4 FIR * UP^2) + noise + bias + leaky_relu * sqrt(2)
// one block per (b, oc); 64x64 outputs; tile with halo in smem.
// out[u,v] = act( sum_{a,e} fk[a,e] * y[u+a-1, v+e-1] + noise[u,v] + bias[oc] )
// ---------------------------------------------------------------------------
__global__ void k_fir(const float* __restrict__ f,
                      const float* __restrict__ noise,
                      const float* __restrict__ bias,
                      float* __restrict__ out) {
    __shared__ float yt[68][69];   // stride 69 => conflict-free column reads
    __shared__ float fk[16];

    int z  = blockIdx.x;
    int b  = z >> 9;
    int oc = z & 511;
    int tid = threadIdx.x;

    if (tid < 16) fk[tid] = f[tid] * 4.0f;   // gain = UP*UP

    const float* ysrc = g_y + ((size_t)(b * OC + oc)) * YS * YS;
    for (int i = tid; i < 68 * 68; i += 256) {
        int r = i / 68, c = i - (i / 68) * 68;
        int h = r - 1, w = c - 1;
        float v = 0.f;
        if (h >= 0 && h < YS && w >= 0 && w < YS) v = ysrc[h * YS + w];
        yt[r][c] = v;
    }
    __syncthreads();

    int u  = tid & 63;            // conflict-free: stride-69 rows, gcd(69-64.. )
    int v0 = (tid >> 6) * 16;     // 4 column groups of 16

    float res[16];
    #pragma unroll
    for (int c = 0; c < 16; c++) res[c] = 0.f;

    #pragma unroll
    for (int a = 0; a < 4; a++) {
        float row[19];
        #pragma unroll
        for (int c = 0; c < 19; c++) row[c] = yt[u + a][v0 + c];
        #pragma unroll
        for (int e = 0; e < 4; e++) {
            float fv = fk[a * 4 + e];
            #pragma unroll
            for (int c = 0; c < 16; c++) res[c] += fv * row[c + e];
        }
    }

    float bs = bias[oc];
    float* orow = out + (((size_t)(b * OC + oc) * RES) + u) * RES + v0;
    #pragma unroll
    for (int c = 0; c < 16; c++) {
        float v = res[c] + noise[u * RES + v0 + c] + bs;
        v = (v > 0.f) ? v : 0.2f * v;
        orow[c] = v * 1.4142135623730951f;
    }
}

// ---------------------------------------------------------------------------
extern "C" void kernel_launch(void* const* d_in, const int* in_sizes, int n_in,
                              void* d_out, int out_size) {
    const float* x     = (const float*)d_in[0];
    const float* w     = (const float*)d_in[1];
    const float* aw    = (const float*)d_in[2];
    const float* ab    = (const float*)d_in[3];
    const float* cw    = (const float*)d_in[4];
    const float* bias  = (const float*)d_in[5];
    const float* noise = (const float*)d_in[6];
    const float* f     = (const float*)d_in[7];
    float* out = (float*)d_out;

    k_styles<<<dim3(64, 16), 256>>>(w, aw, ab);
    k_wsum  <<<dim3(1024),   256>>>(cw);
    k_dcoef <<<dim3(64, 16), 256>>>();
    k_conv  <<<dim3(5, 5, BATCH * (OC / OCT)), 256>>>(x, cw);
    k_fir   <<<dim3(BATCH * OC), 256>>>(f, noise, bias, out);
}

// round 3
// speedup vs baseline: 4.6617x; 4.6617x over previous
#include <cuda_runtime.h>
#include <cuda_bf16.h>
#include <cstdint>

#define BATCH 16
#define IC    512
#define OC    512
#define WD    512
#define HIN   32
#define RES   64
#define YS    65

#define MM   1024            // spatial positions per sample (32*32)
#define KK   512             // IC
#define NN   4608            // OC * 9 taps

// GEMM tiling
#define TM   128
#define TN   128
#define TKC  64              // k per chunk (64 bf16 = 128B rows, swizzled)
#define NKC  (KK / TKC)      // 8 chunks

// ---------------- device scratch (static: no runtime allocation) -----------
__device__ float g_styles[BATCH * IC];
__device__ float g_dcoef [BATCH * OC];
__device__ float g_wsum  [OC * IC];
__device__ __nv_bfloat16 g_Ah[(size_t)BATCH * MM * KK];   // 16MB  A hi  [b][m][k]
__device__ __nv_bfloat16 g_Al[(size_t)BATCH * MM * KK];   // 16MB  A lo
__device__ __nv_bfloat16 g_Bh[(size_t)NN * KK];           // 4.5MB B hi  [n][k]
__device__ __nv_bfloat16 g_Bl[(size_t)NN * KK];           // 4.5MB B lo
__device__ float g_ct[(size_t)BATCH * NN * MM];           // 302MB C^T  [b][n][m]

// ---------------- helpers ----------------------------------------------------
__device__ __forceinline__ uint32_t smem_u32(const void* p) {
    uint32_t a;
    asm("{ .reg .u64 t; cvta.to.shared.u64 t, %1; cvt.u32.u64 %0, t; }"
        : "=r"(a) : "l"(p));
    return a;
}

__device__ __forceinline__ void cp16(uint32_t saddr, const void* g) {
    asm volatile("cp.async.cg.shared.global [%0], [%1], 16;"
                 :: "r"(saddr), "l"(g) : "memory");
}

__device__ __forceinline__ void ldsm4(uint32_t* r, uint32_t addr) {
    asm volatile("ldmatrix.sync.aligned.m8n8.x4.shared.b16 {%0,%1,%2,%3}, [%4];"
                 : "=r"(r[0]), "=r"(r[1]), "=r"(r[2]), "=r"(r[3]) : "r"(addr));
}

__device__ __forceinline__ void mma_bf16(float* d, const uint32_t* a,
                                         uint32_t b0, uint32_t b1) {
    asm volatile(
        "mma.sync.aligned.m16n8k16.row.col.f32.bf16.bf16.f32 "
        "{%0,%1,%2,%3}, {%4,%5,%6,%7}, {%8,%9}, {%0,%1,%2,%3};"
        : "+f"(d[0]), "+f"(d[1]), "+f"(d[2]), "+f"(d[3])
        : "r"(a[0]), "r"(a[1]), "r"(a[2]), "r"(a[3]), "r"(b0), "r"(b1));
}

// SMEM layout for GEMM (dynamic): per stage 64KB = A(hi,lo) 32KB + B(hi,lo) 32KB
#define SA(st, part)  ((st) * 65536u + (part) * 16384u)
#define SB(st, part)  ((st) * 65536u + 32768u + (part) * 16384u)
#define SM_TOTAL_G    131072u

// ---------------------------------------------------------------------------
// K1: styles[b,ic]
// ---------------------------------------------------------------------------
__global__ void k_styles(const float* __restrict__ w,
                         const float* __restrict__ aw,
                         const float* __restrict__ ab) {
    int b = blockIdx.y, warp = threadIdx.x >> 5, lane = threadIdx.x & 31;
    int ic = blockIdx.x * 8 + warp;
    const float* wrow = w  + (size_t)b  * WD;
    const float* arow = aw + (size_t)ic * WD;
    float s = 0.f;
    #pragma unroll 4
    for (int k = lane; k < WD; k += 32) s += wrow[k] * arow[k];
    #pragma unroll
    for (int o = 16; o; o >>= 1) s += __shfl_xor_sync(0xffffffffu, s, o);
    if (lane == 0)
        g_styles[b * IC + ic] = s * 0.04419417382415922f + ab[ic];
}

// ---------------------------------------------------------------------------
// K2: wsum[oc,ic] = sum_{3x3} w^2
// ---------------------------------------------------------------------------
__global__ void k_wsum(const float* __restrict__ cw) {
    int idx = blockIdx.x * blockDim.x + threadIdx.x;
    if (idx >= OC * IC) return;
    const float* p = cw + (size_t)idx * 9;
    float s = 0.f;
    #pragma unroll
    for (int k = 0; k < 9; k++) { float v = p[k]; s += v * v; }
    g_wsum[idx] = s;
}

// ---------------------------------------------------------------------------
// K3: dcoef[b,oc]
// ---------------------------------------------------------------------------
__global__ void k_dcoef() {
    int b = blockIdx.y, warp = threadIdx.x >> 5, lane = threadIdx.x & 31;
    int oc = blockIdx.x * 8 + warp;
    float s = 0.f;
    #pragma unroll 4
    for (int ic = lane; ic < IC; ic += 32) {
        float st = g_styles[b * IC + ic];
        s += st * st * g_wsum[oc * IC + ic];
    }
    #pragma unroll
    for (int o = 16; o; o >>= 1) s += __shfl_xor_sync(0xffffffffu, s, o);
    if (lane == 0) g_dcoef[b * OC + oc] = rsqrtf(s + 1e-8f);
}

// ---------------------------------------------------------------------------
// K4: A prep — x[b][ic][m] -> A[b][m][k], style-scaled, bf16 hi/lo split
// ---------------------------------------------------------------------------
__global__ void k_prepA(const float* __restrict__ x) {
    __shared__ float s[64][65];
    int b = blockIdx.z;
    int m0 = blockIdx.x * 64;
    int k0 = blockIdx.y * 64;
    int tid = threadIdx.x;
    for (int l = tid; l < 4096; l += 256) {
        int ii = l >> 6, jj = l & 63;
        float v = x[(((size_t)b * IC + k0 + ii) << 10) + m0 + jj]
                  * g_styles[b * IC + k0 + ii];
        s[jj][ii] = v;
    }
    __syncthreads();
    for (int l = tid; l < 4096; l += 256) {
        int mm = l >> 6, kk = l & 63;
        float v = s[mm][kk];
        __nv_bfloat16 h = __float2bfloat16(v);
        float r = v - __bfloat162float(h);
        size_t idx = (((size_t)b * MM + m0 + mm) << 9) + k0 + kk;
        g_Ah[idx] = h;
        g_Al[idx] = __float2bfloat16(r);
    }
}

// ---------------------------------------------------------------------------
// K5: B prep — cw[oc][ic][tap] -> B[n=oc*9+tap][k=ic], bf16 hi/lo split
// ---------------------------------------------------------------------------
__global__ void k_prepB(const float* __restrict__ cw) {
    __shared__ float s[4608];
    int oc = blockIdx.x, tid = threadIdx.x;
    for (int l = tid; l < 4608; l += 256) s[l] = cw[(size_t)oc * 4608 + l];
    __syncthreads();
    for (int l = tid; l < 4608; l += 256) {
        int t = l / 512, k = l & 511;
        float v = s[k * 9 + t];
        __nv_bfloat16 h = __float2bfloat16(v);
        float r = v - __bfloat162float(h);
        size_t idx = (((size_t)oc * 9 + t) << 9) + k;
        g_Bh[idx] = h;
        g_Bl[idx] = __float2bfloat16(r);
    }
}

// ---------------------------------------------------------------------------
// K6: mma.sync GEMM.  g_ct[b][n][m] = sum_k A[b][m][k]*B[n][k], 3xbf16 split.
// CTA 128x128, 8 warps (2m x 4n), warp tile 64x32, 2-stage cp.async pipeline.
// ---------------------------------------------------------------------------
__device__ __forceinline__ void load_chunk_g(uint32_t sb, int b, int m0, int n0,
                                             int c, int st, int tid) {
    size_t kc0 = (size_t)c * TKC;
    #pragma unroll
    for (int i = 0; i < 8; i++) {          // A: 2 parts x 128 rows x 8 chunks
        int l = tid + i * 256;             // 0..2047
        int part = l >> 10, r = (l >> 3) & 127, ch = l & 7;
        const __nv_bfloat16* gp = (part ? g_Al : g_Ah)
            + (((size_t)b * MM + m0 + r) << 9) + kc0 + ch * 8;
        cp16(sb + SA(st, part) + r * 128u + ((ch ^ (r & 7)) * 16u), gp);
    }
    #pragma unroll
    for (int i = 0; i < 8; i++) {          // B: 2 parts x 128 rows x 8 chunks
        int l = tid + i * 256;
        int part = l >> 10, r = (l >> 3) & 127, ch = l & 7;
        const __nv_bfloat16* gp = (part ? g_Bl : g_Bh)
            + (((size_t)(n0 + r)) << 9) + kc0 + ch * 8;
        cp16(sb + SB(st, part) + r * 128u + ((ch ^ (r & 7)) * 16u), gp);
    }
    asm volatile("cp.async.commit_group;" ::: "memory");
}

__global__ void __launch_bounds__(256, 1) k_gemm() {
    extern __shared__ char smem[];
    uint32_t sb = smem_u32(smem);
    int tid = threadIdx.x, wid = tid >> 5, lane = tid & 31;
    int n0 = blockIdx.x * TN;
    int m0 = blockIdx.y * TM;
    int b  = blockIdx.z;

    int wm0 = (wid >> 2) * 64;     // warp m offset within CTA
    int wn0 = (wid & 3) * 32;      // warp n offset within CTA

    // ldmatrix per-lane row geometry
    int mat = lane >> 3, rr = lane & 7;
    int lr  = (mat & 1) * 8 + rr;  // row within 16-row tile
    int chi = mat >> 1;            // k 16B-chunk offset within k16 step

    uint32_t arow = (uint32_t)(wm0 + lr);
    uint32_t brow = (uint32_t)(wn0 + lr);
    uint32_t aswz = arow & 7;      // invariant under +16*mi
    uint32_t bswz = brow & 7;

    float acc[4][4][4];
    #pragma unroll
    for (int i = 0; i < 4; i++)
        #pragma unroll
        for (int j = 0; j < 4; j++)
            #pragma unroll
            for (int q = 0; q < 4; q++) acc[i][j][q] = 0.f;

    load_chunk_g(sb, b, m0, n0, 0, 0, tid);

    #pragma unroll 1
    for (int c = 0; c < NKC; c++) {
        int st = c & 1;
        if (c + 1 < NKC) load_chunk_g(sb, b, m0, n0, c + 1, st ^ 1, tid);
        if (c + 1 < NKC)
            asm volatile("cp.async.wait_group 1;" ::: "memory");
        else
            asm volatile("cp.async.wait_group 0;" ::: "memory");
        __syncthreads();

        #pragma unroll
        for (int s = 0; s < 4; s++) {
            uint32_t kchunk = (uint32_t)(2 * s + chi);
            uint32_t acol = ((kchunk ^ aswz) * 16u);
            uint32_t bcol = ((kchunk ^ bswz) * 16u);

            uint32_t af[2][4][4];
            #pragma unroll
            for (int p = 0; p < 2; p++)
                #pragma unroll
                for (int mi = 0; mi < 4; mi++)
                    ldsm4(af[p][mi],
                          sb + SA(st, p) + (arow + mi * 16u) * 128u + acol);

            uint32_t bf[2][2][4];
            #pragma unroll
            for (int p = 0; p < 2; p++)
                #pragma unroll
                for (int nj = 0; nj < 2; nj++)
                    ldsm4(bf[p][nj],
                          sb + SB(st, p) + (brow + nj * 16u) * 128u + bcol);

            #pragma unroll
            for (int mi = 0; mi < 4; mi++)
                #pragma unroll
                for (int nj = 0; nj < 4; nj++) {
                    uint32_t b0h = bf[0][nj >> 1][(nj & 1)];
                    uint32_t b1h = bf[0][nj >> 1][(nj & 1) + 2];
                    uint32_t b0l = bf[1][nj >> 1][(nj & 1)];
                    uint32_t b1l = bf[1][nj >> 1][(nj & 1) + 2];
                    mma_bf16(acc[mi][nj], af[0][mi], b0h, b1h);  // hi*hi
                    mma_bf16(acc[mi][nj], af[0][mi], b0l, b1l);  // hi*lo
                    mma_bf16(acc[mi][nj], af[1][mi], b0h, b1h);  // lo*hi
                }
        }
        __syncthreads();
    }

    // epilogue: store transposed to g_ct[b][n][m]
    int g  = lane >> 2;
    int cq = (lane & 3) * 2;
    #pragma unroll
    for (int mi = 0; mi < 4; mi++) {
        #pragma unroll
        for (int nj = 0; nj < 4; nj++) {
            int nb = n0 + wn0 + nj * 8 + cq;
            int mb = m0 + wm0 + mi * 16 + g;
            float* d0 = g_ct + ((size_t)b * NN + nb) * MM + mb;
            d0[0]           = acc[mi][nj][0];
            d0[MM]          = acc[mi][nj][1];
            d0[8]           = acc[mi][nj][2];
            d0[MM + 8]      = acc[mi][nj][3];
        }
    }
}

// ---------------------------------------------------------------------------
// K7: fused tap-gather (transpose-conv assembly) + upfirdn 4x4 + noise + bias
//     + lrelu*sqrt(2).  One block per (b, oc).
// ---------------------------------------------------------------------------
#define SMF_YT   36864u                  // after 9*1024 floats
#define SMF_FK   (SMF_YT + 18768u)       // after 68*69 floats
#define SM_TOTAL_F (SMF_FK + 64u)

__global__ void __launch_bounds__(256) k_fir(const float* __restrict__ f,
                                             const float* __restrict__ noise,
                                             const float* __restrict__ bias,
                                             float* __restrict__ out) {
    extern __shared__ char smemf[];
    float* sct = (float*)smemf;                    // [9][1024]
    float* yt  = (float*)(smemf + SMF_YT);         // [68][69]
    float* fk  = (float*)(smemf + SMF_FK);

    int z = blockIdx.x;
    int b = z >> 9;
    int oc = z & 511;
    int tid = threadIdx.x;

    if (tid < 16) fk[tid] = f[tid] * 4.0f;
    float dco = g_dcoef[b * OC + oc];

    const float* csrc = g_ct + ((size_t)b * NN + (size_t)oc * 9) * MM;
    for (int i = tid; i < 9 * MM; i += 256) sct[i] = csrc[i];
    __syncthreads();

    // y tile (65x65 valid) at yt[p+1][q+1]
    for (int idx = tid; idx < 68 * 68; idx += 256) {
        int r = idx / 68, cq = idx - (idx / 68) * 68;
        int p = r - 1, q = cq - 1;
        float s = 0.f;
        int ilo = (p & 1) ? 1 : 0, istep = (p & 1) ? 4 : 2;
        for (int i = ilo; i <= 2; i += istep) {
            int ph = p - i;
            if (ph < 0) continue;
            int h = ph >> 1;
            if (h >= HIN) continue;
            int jlo = (q & 1) ? 1 : 0, jstep = (q & 1) ? 4 : 2;
            for (int j = jlo; j <= 2; j += jstep) {
                int qw = q - j;
                if (qw < 0) continue;
                int w = qw >> 1;
                if (w >= HIN) continue;
                s += sct[(i * 3 + j) * MM + h * 32 + w];
            }
        }
        yt[r * 69 + cq] = s * dco;
    }
    __syncthreads();

    int u  = tid & 63;
    int v0 = (tid >> 6) * 16;

    float res[16];
    #pragma unroll
    for (int c = 0; c < 16; c++) res[c] = 0.f;

    #pragma unroll
    for (int a = 0; a < 4; a++) {
        float row[19];
        #pragma unroll
        for (int c = 0; c < 19; c++) row[c] = yt[(u + a) * 69 + v0 + c];
        #pragma unroll
        for (int e = 0; e < 4; e++) {
            float fv = fk[a * 4 + e];
            #pragma unroll
            for (int c = 0; c < 16; c++) res[c] += fv * row[c + e];
        }
    }

    float bs = bias[oc];
    float* orow = out + (((size_t)(b * OC + oc) * RES) + u) * RES + v0;
    #pragma unroll
    for (int c = 0; c < 16; c++) {
        float v = res[c] + noise[u * RES + v0 + c] + bs;
        v = (v > 0.f) ? v : 0.2f * v;
        orow[c] = v * 1.4142135623730951f;
    }
}

// ---------------------------------------------------------------------------
extern "C" void kernel_launch(void* const* d_in, const int* in_sizes, int n_in,
                              void* d_out, int out_size) {
    const float* x     = (const float*)d_in[0];
    const float* w     = (const float*)d_in[1];
    const float* aw    = (const float*)d_in[2];
    const float* ab    = (const float*)d_in[3];
    const float* cw    = (const float*)d_in[4];
    const float* bias  = (const float*)d_in[5];
    const float* noise = (const float*)d_in[6];
    const float* f     = (const float*)d_in[7];
    float* out = (float*)d_out;

    cudaFuncSetAttribute(k_gemm, cudaFuncAttributeMaxDynamicSharedMemorySize, SM_TOTAL_G);
    cudaFuncSetAttribute(k_fir,  cudaFuncAttributeMaxDynamicSharedMemorySize, SM_TOTAL_F);

    k_styles<<<dim3(64, 16), 256>>>(w, aw, ab);
    k_wsum  <<<dim3(1024),   256>>>(cw);
    k_dcoef <<<dim3(64, 16), 256>>>();
    k_prepA <<<dim3(16, 8, 16), 256>>>(x);
    k_prepB <<<dim3(512),    256>>>(cw);
    k_gemm  <<<dim3(NN / TN, MM / TM, BATCH), 256, SM_TOTAL_G>>>();
    k_fir   <<<dim3(BATCH * OC), 256, SM_TOTAL_F>>>(f, noise, bias, out);
}